// round 5
// baseline (speedup 1.0000x reference)
#include <cuda_runtime.h>
#include <cuda_fp16.h>
#include <cuda_bf16.h>
#include <cstdint>

// Problem constants (fixed by the dataset)
#define C_DIM 128   // input feature dim
#define H_DIM 64    // hidden dim
#define E_FEAT 16   // edge feature dim
#define ATT_LD 144  // 2*H + E_FEAT

#define MAXN 65536
#define MAXE 1048576

// Scratch
__device__ float  g_h[MAXN * H_DIM];     // h = fc(x)                [N,64] fp32
__device__ __half g_a1h[MAXN * H_DIM];   // a1 = h @ W1^T            [N,64] fp16
__device__ __half g_a2h[MAXN * H_DIM];   // a2 = h @ W2^T            [N,64] fp16
__device__ __half g_b3[MAXE * H_DIM];    // b3 = W3 @ ea + att_b     [E,64] fp16
__device__ int    g_idx64;               // 1 if edge_index is int64

// ---------------------------------------------------------------------------
// Detect edge_index dtype (int32 vs int64) — see R1 post-mortem.
// ---------------------------------------------------------------------------
__global__ void detect_idx_kernel(const long long* __restrict__ ei, int N)
{
    if (threadIdx.x == 0 && blockIdx.x == 0) {
        int is64 = 1;
        for (int k = 0; k < 128; k++) {
            long long v = ei[k];
            if (v < 0 || v >= (long long)N) { is64 = 0; break; }
        }
        g_idx64 = is64;
    }
}

// ---------------------------------------------------------------------------
// GEMM 1: h = x @ fc_w^T + fc_b. BM=128, 256 thr, 8x4 microtile. fp32 out.
// ---------------------------------------------------------------------------
#define BM 128
#define BK 16

__global__ __launch_bounds__(256) void gemm_h_kernel(
    const float* __restrict__ A,      // [M,128]
    const float* __restrict__ W,      // [64,128]
    const float* __restrict__ bias,   // [64]
    float* __restrict__ out,          // [M,64]
    int M)
{
    __shared__ float As[BM][BK + 4];
    __shared__ float Bs[BK][64];

    const int tid = threadIdx.x;
    const int bm = blockIdx.x * BM;
    const int tx = tid & 15;
    const int ty = tid >> 4;

    float acc[8][4];
#pragma unroll
    for (int r = 0; r < 8; r++)
#pragma unroll
        for (int c = 0; c < 4; c++) acc[r][c] = 0.f;

    for (int k0 = 0; k0 < C_DIM; k0 += BK) {
#pragma unroll
        for (int it = 0; it < 2; it++) {
            int m = (tid >> 2) + it * 64;
            int kk = (tid & 3) * 4;
            float4 v = make_float4(0.f, 0.f, 0.f, 0.f);
            if (bm + m < M)
                v = *(const float4*)&A[(size_t)(bm + m) * C_DIM + k0 + kk];
            *(float4*)&As[m][kk] = v;
        }
        {
            int n = tid >> 2;
            int kk = (tid & 3) * 4;
            float4 v = *(const float4*)&W[(size_t)n * C_DIM + k0 + kk];
            Bs[kk + 0][n] = v.x;  Bs[kk + 1][n] = v.y;
            Bs[kk + 2][n] = v.z;  Bs[kk + 3][n] = v.w;
        }
        __syncthreads();

#pragma unroll
        for (int kk = 0; kk < BK; kk++) {
            float b4[4];
            *(float4*)b4 = *(const float4*)&Bs[kk][tx * 4];
            float a8[8];
#pragma unroll
            for (int r = 0; r < 8; r++) a8[r] = As[ty * 8 + r][kk];
#pragma unroll
            for (int r = 0; r < 8; r++)
#pragma unroll
                for (int c = 0; c < 4; c++)
                    acc[r][c] = fmaf(a8[r], b4[c], acc[r][c]);
        }
        __syncthreads();
    }

#pragma unroll
    for (int r = 0; r < 8; r++) {
        int m = bm + ty * 8 + r;
        if (m < M) {
#pragma unroll
            for (int c = 0; c < 4; c++) {
                int n = tx * 4 + c;
                out[(size_t)m * H_DIM + n] = acc[r][c] + bias[n];
            }
        }
    }
}

// ---------------------------------------------------------------------------
// GEMM 2 (fused a1|a2, fp16 out): for q in [0,128):
//   weight element (out col q, k idx m) = att_w[(q&63)*144 + (q>>6)*64 + m]
//   q <  64 -> a1h[n][q],  q >= 64 -> a2h[n][q-64]
// BM=128, BN=128, BK=16, K=64, 256 threads, 8x8 microtile.
// ---------------------------------------------------------------------------
struct alignas(16) H8 { __half2 h[4]; };

__global__ __launch_bounds__(256) void gemm_a12_kernel(
    const float* __restrict__ h,      // [M,64]
    const float* __restrict__ att_w,  // [64,144]
    __half* __restrict__ a1h,         // [M,64]
    __half* __restrict__ a2h,         // [M,64]
    int M)
{
    __shared__ float As[BM][BK + 4];
    __shared__ float Bs[BK][128];

    const int tid = threadIdx.x;
    const int bm = blockIdx.x * BM;
    const int tx = tid & 15;
    const int ty = tid >> 4;

    float acc[8][8];
#pragma unroll
    for (int r = 0; r < 8; r++)
#pragma unroll
        for (int c = 0; c < 8; c++) acc[r][c] = 0.f;

    for (int k0 = 0; k0 < H_DIM; k0 += BK) {
#pragma unroll
        for (int it = 0; it < 2; it++) {
            int m = (tid >> 2) + it * 64;
            int kk = (tid & 3) * 4;
            float4 v = make_float4(0.f, 0.f, 0.f, 0.f);
            if (bm + m < M)
                v = *(const float4*)&h[(size_t)(bm + m) * H_DIM + k0 + kk];
            *(float4*)&As[m][kk] = v;
        }
        {
            int q = tid >> 1;
            int kk = (tid & 1) * 8;
            size_t base = (size_t)(q & 63) * ATT_LD + (q >> 6) * 64 + k0 + kk;
            float4 v0 = *(const float4*)&att_w[base];
            float4 v1 = *(const float4*)&att_w[base + 4];
            Bs[kk + 0][q] = v0.x; Bs[kk + 1][q] = v0.y;
            Bs[kk + 2][q] = v0.z; Bs[kk + 3][q] = v0.w;
            Bs[kk + 4][q] = v1.x; Bs[kk + 5][q] = v1.y;
            Bs[kk + 6][q] = v1.z; Bs[kk + 7][q] = v1.w;
        }
        __syncthreads();

#pragma unroll
        for (int kk = 0; kk < BK; kk++) {
            float b8[8];
            *(float4*)&b8[0] = *(const float4*)&Bs[kk][tx * 8];
            *(float4*)&b8[4] = *(const float4*)&Bs[kk][tx * 8 + 4];
            float a8[8];
#pragma unroll
            for (int r = 0; r < 8; r++) a8[r] = As[ty * 8 + r][kk];
#pragma unroll
            for (int r = 0; r < 8; r++)
#pragma unroll
                for (int c = 0; c < 8; c++)
                    acc[r][c] = fmaf(a8[r], b8[c], acc[r][c]);
        }
        __syncthreads();
    }

    const int q = tx * 8;
#pragma unroll
    for (int r = 0; r < 8; r++) {
        int m = bm + ty * 8 + r;
        if (m < M) {
            H8 v;
            v.h[0] = __floats2half2_rn(acc[r][0], acc[r][1]);
            v.h[1] = __floats2half2_rn(acc[r][2], acc[r][3]);
            v.h[2] = __floats2half2_rn(acc[r][4], acc[r][5]);
            v.h[3] = __floats2half2_rn(acc[r][6], acc[r][7]);
            __half* dst = (q < 64) ? (a1h + (size_t)m * H_DIM + q)
                                   : (a2h + (size_t)m * H_DIM + (q - 64));
            *(H8*)dst = v;
        }
    }
}

// ---------------------------------------------------------------------------
// GEMM 3: b3[e][k] = sum_c ea[e][c] * att_w[k][128+c] + att_b[k], fp16 out.
// Block 256 threads = 64 edges; thread handles 4 edges x 4 channels.
// ---------------------------------------------------------------------------
__global__ __launch_bounds__(256) void gemm_b3_kernel(
    const float* __restrict__ ea,     // [E,16]
    const float* __restrict__ att_w,  // [64,144]
    const float* __restrict__ att_b,  // [64]
    __half* __restrict__ b3,          // [E,64]
    int E)
{
    __shared__ float eas[64][17];
    __shared__ float W3s[16][68];

    const int tid = threadIdx.x;
    const int eb = blockIdx.x * 64;

    // ea tile: 64 edges x 16 = 1024 floats, coalesced 4/thread
#pragma unroll
    for (int it = 0; it < 4; it++) {
        int x = tid + it * 256;          // 0..1023
        int er = x >> 4, ec = x & 15;
        int ee = eb + er;
        eas[er][ec] = (ee < E) ? ea[(size_t)ee * E_FEAT + ec] : 0.f;
    }
    // W3 transpose: W3s[c][k] = att_w[k*144 + 128 + c]
#pragma unroll
    for (int it = 0; it < 4; it++) {
        int x = tid + it * 256;
        int c = x >> 6, k = x & 63;
        W3s[c][k] = att_w[(size_t)k * ATT_LD + 2 * H_DIM + c];
    }
    __syncthreads();

    const int er = tid >> 4;             // 0..15 -> edges 4*er..4*er+3
    const int c0 = (tid & 15) * 4;       // channels c0..c0+3
    const float4 bias = *(const float4*)&att_b[c0];

    float acc[4][4];
#pragma unroll
    for (int u = 0; u < 4; u++) {
        acc[u][0] = bias.x; acc[u][1] = bias.y;
        acc[u][2] = bias.z; acc[u][3] = bias.w;
    }

#pragma unroll
    for (int c = 0; c < E_FEAT; c++) {
        float4 w = *(const float4*)&W3s[c][c0];
#pragma unroll
        for (int u = 0; u < 4; u++) {
            float a = eas[4 * er + u][c];
            acc[u][0] = fmaf(w.x, a, acc[u][0]);
            acc[u][1] = fmaf(w.y, a, acc[u][1]);
            acc[u][2] = fmaf(w.z, a, acc[u][2]);
            acc[u][3] = fmaf(w.w, a, acc[u][3]);
        }
    }

#pragma unroll
    for (int u = 0; u < 4; u++) {
        int e = eb + 4 * er + u;
        if (e < E) {
            __half2 p0 = __floats2half2_rn(acc[u][0], acc[u][1]);
            __half2 p1 = __floats2half2_rn(acc[u][2], acc[u][3]);
            __half2* dst = (__half2*)&b3[(size_t)e * H_DIM + c0];
            dst[0] = p0;
            dst[1] = p1;
        }
    }
}

// ---------------------------------------------------------------------------
// Edge phase v3: half-warp per edge, 4 channels per lane, 2x unroll.
//   s = a1[i] + a2[j] + b3[e]   (fp16 gathers, fp32 math)
//   out[i] += h[j] * leaky(s)   (red.global.add.v4.f32)
// No shuffles, no smem — pure load/compute/RED.
// ---------------------------------------------------------------------------
__device__ __forceinline__ float4 h4_to_f4(uint2 v)
{
    __half2 lo = *(__half2*)&v.x;
    __half2 hi = *(__half2*)&v.y;
    float2 l = __half22float2(lo);
    float2 h = __half22float2(hi);
    return make_float4(l.x, l.y, h.x, h.y);
}

__device__ __forceinline__ float4 leaky4(float4 s)
{
    s.x = fmaxf(s.x, 0.f) + 0.2f * fminf(s.x, 0.f);
    s.y = fmaxf(s.y, 0.f) + 0.2f * fminf(s.y, 0.f);
    s.z = fmaxf(s.z, 0.f) + 0.2f * fminf(s.z, 0.f);
    s.w = fmaxf(s.w, 0.f) + 0.2f * fminf(s.w, 0.f);
    return s;
}

__device__ __forceinline__ void red_add_v4(float* p, float4 v)
{
    asm volatile("red.global.add.v4.f32 [%0], {%1, %2, %3, %4};"
                 :: "l"(p), "f"(v.x), "f"(v.y), "f"(v.z), "f"(v.w)
                 : "memory");
}

__global__ __launch_bounds__(256) void edge_kernel_v3(
    const void* __restrict__ ei_raw,     // [2,E] int32 or int64
    const __half* __restrict__ b3,       // [E,64]
    const float* __restrict__ h,         // [N,64]
    const __half* __restrict__ a1h,      // [N,64]
    const __half* __restrict__ a2h,      // [N,64]
    float* __restrict__ out,             // [N,64]
    int E)
{
    const int tid   = threadIdx.x;
    const int lane  = tid & 31;
    const int glane = lane & 15;
    const int group = lane >> 4;
    const int hw    = (blockIdx.x * (blockDim.x >> 5) + (tid >> 5)) * 2 + group;
    const int T     = gridDim.x * (blockDim.x >> 5) * 2;   // total half-warps
    const int k0    = 4 * glane;

    const int is64 = g_idx64;
    const long long* ei64 = (const long long*)ei_raw;
    const int*       ei32 = (const int*)ei_raw;

    const uint2*  a1v = (const uint2*)a1h;   // [N][16] x 8B
    const uint2*  a2v = (const uint2*)a2h;
    const uint2*  b3v = (const uint2*)b3;    // [E][16] x 8B
    const float4* h4  = (const float4*)h;    // [N][16] x 16B

    for (int e1 = hw; e1 < E; e1 += 2 * T) {
        const int  e2  = e1 + T;
        const bool v2  = e2 < E;
        const int  e2c = v2 ? e2 : e1;

        int i1, j1, i2, j2;
        if (is64) {
            i1 = (int)ei64[e1];  j1 = (int)ei64[(size_t)E + e1];
            i2 = (int)ei64[e2c]; j2 = (int)ei64[(size_t)E + e2c];
        } else {
            i1 = ei32[e1];  j1 = ei32[(size_t)E + e1];
            i2 = ei32[e2c]; j2 = ei32[(size_t)E + e2c];
        }

        const uint2  B1 = b3v[(size_t)e1  * 16 + glane];
        const uint2  B2 = b3v[(size_t)e2c * 16 + glane];
        const uint2  A1a = a1v[(size_t)i1 * 16 + glane];
        const uint2  A2a = a2v[(size_t)j1 * 16 + glane];
        const float4 HJ1 = h4[(size_t)j1 * 16 + glane];
        const uint2  A1b = a1v[(size_t)i2 * 16 + glane];
        const uint2  A2b = a2v[(size_t)j2 * 16 + glane];
        const float4 HJ2 = h4[(size_t)j2 * 16 + glane];

        float4 fa = h4_to_f4(A1a), fb = h4_to_f4(A2a), fc = h4_to_f4(B1);
        float4 s1 = make_float4(fa.x + fb.x + fc.x, fa.y + fb.y + fc.y,
                                fa.z + fb.z + fc.z, fa.w + fb.w + fc.w);
        float4 ga = h4_to_f4(A1b), gb = h4_to_f4(A2b), gc = h4_to_f4(B2);
        float4 s2 = make_float4(ga.x + gb.x + gc.x, ga.y + gb.y + gc.y,
                                ga.z + gb.z + gc.z, ga.w + gb.w + gc.w);

        s1 = leaky4(s1);
        s2 = leaky4(s2);

        float4 m1 = make_float4(HJ1.x * s1.x, HJ1.y * s1.y,
                                HJ1.z * s1.z, HJ1.w * s1.w);
        red_add_v4(&out[(size_t)i1 * H_DIM + k0], m1);

        if (v2) {
            float4 m2 = make_float4(HJ2.x * s2.x, HJ2.y * s2.y,
                                    HJ2.z * s2.z, HJ2.w * s2.w);
            red_add_v4(&out[(size_t)i2 * H_DIM + k0], m2);
        }
    }
}

// ---------------------------------------------------------------------------
// Launch
// Inputs (metadata order): x, edge_index, edge_attr, fc_w, fc_b, att_w, att_b
// ---------------------------------------------------------------------------
extern "C" void kernel_launch(void* const* d_in, const int* in_sizes, int n_in,
                              void* d_out, int out_size)
{
    const float* x     = (const float*)d_in[0];
    const void*  ei    = d_in[1];
    const float* ea    = (const float*)d_in[2];
    const float* fc_w  = (const float*)d_in[3];
    const float* fc_b  = (const float*)d_in[4];
    const float* att_w = (const float*)d_in[5];
    const float* att_b = (const float*)d_in[6];
    float*       out   = (float*)d_out;

    const int N = in_sizes[0] / C_DIM;
    const int E = in_sizes[1] / 2;

    float*  hbuf  = nullptr;
    __half* a1buf = nullptr;
    __half* a2buf = nullptr;
    __half* b3buf = nullptr;
    cudaGetSymbolAddress((void**)&hbuf,  g_h);
    cudaGetSymbolAddress((void**)&a1buf, g_a1h);
    cudaGetSymbolAddress((void**)&a2buf, g_a2h);
    cudaGetSymbolAddress((void**)&b3buf, g_b3);

    detect_idx_kernel<<<1, 32>>>((const long long*)ei, N);

    const int gblocks = (N + BM - 1) / BM;

    // zero output (async memset on default stream — graph-capturable)
    cudaMemsetAsync(out, 0, (size_t)N * H_DIM * sizeof(float));

    // h = x @ fc_w^T + fc_b                    [N,64]
    gemm_h_kernel<<<gblocks, 256>>>(x, fc_w, fc_b, hbuf, N);
    // a1|a2 = h @ [W1|W2]^T  (fp16)            [N,64]x2
    gemm_a12_kernel<<<gblocks, 256>>>(hbuf, att_w, a1buf, a2buf, N);
    // b3 = ea @ W3^T + att_b (fp16)            [E,64]
    gemm_b3_kernel<<<(E + 63) / 64, 256>>>(ea, att_w, att_b, b3buf, E);

    // edge scatter
    edge_kernel_v3<<<1480, 256>>>(ei, b3buf, hbuf, a1buf, a2buf, out, E);
}

// round 6
// speedup vs baseline: 1.0186x; 1.0186x over previous
#include <cuda_runtime.h>
#include <cuda_fp16.h>
#include <cuda_bf16.h>
#include <cstdint>

// Problem constants (fixed by the dataset)
#define C_DIM 128   // input feature dim
#define H_DIM 64    // hidden dim
#define E_FEAT 16   // edge feature dim
#define ATT_LD 144  // 2*H + E_FEAT

#define MAXN 65536

// Scratch
__device__ float  g_h[MAXN * H_DIM];        // h = fc(x)      [N,64] fp32 (gemm_a12 input)
__device__ __half g_a1h[MAXN * H_DIM];      // a1 = h @ W1^T  [N,64] fp16
// Packed per-node j-side record: for lane g (0..15), 16 bytes:
//   [a2 ch 4g..4g+3 (4 x fp16) | h ch 4g..4g+3 (4 x fp16)]
__device__ __align__(16) __half g_jpack[MAXN * 2 * H_DIM];  // [N][256B]

// ---------------------------------------------------------------------------
// GEMM 1: h = x @ fc_w^T + fc_b. Writes fp32 h AND fp16 h into jpack.
// BM=128, 256 thr, 8x4 microtile.
// ---------------------------------------------------------------------------
#define BM 128
#define BK 16

__global__ __launch_bounds__(256) void gemm_h_kernel(
    const float* __restrict__ A,      // [M,128]
    const float* __restrict__ W,      // [64,128]
    const float* __restrict__ bias,   // [64]
    float* __restrict__ out,          // [M,64] fp32
    __half* __restrict__ jpack,       // [M][256B]
    int M)
{
    __shared__ float As[BM][BK + 4];
    __shared__ float Bs[BK][64];

    const int tid = threadIdx.x;
    const int bm = blockIdx.x * BM;
    const int tx = tid & 15;
    const int ty = tid >> 4;

    float acc[8][4];
#pragma unroll
    for (int r = 0; r < 8; r++)
#pragma unroll
        for (int c = 0; c < 4; c++) acc[r][c] = 0.f;

    for (int k0 = 0; k0 < C_DIM; k0 += BK) {
#pragma unroll
        for (int it = 0; it < 2; it++) {
            int m = (tid >> 2) + it * 64;
            int kk = (tid & 3) * 4;
            float4 v = make_float4(0.f, 0.f, 0.f, 0.f);
            if (bm + m < M)
                v = *(const float4*)&A[(size_t)(bm + m) * C_DIM + k0 + kk];
            *(float4*)&As[m][kk] = v;
        }
        {
            int n = tid >> 2;
            int kk = (tid & 3) * 4;
            float4 v = *(const float4*)&W[(size_t)n * C_DIM + k0 + kk];
            Bs[kk + 0][n] = v.x;  Bs[kk + 1][n] = v.y;
            Bs[kk + 2][n] = v.z;  Bs[kk + 3][n] = v.w;
        }
        __syncthreads();

#pragma unroll
        for (int kk = 0; kk < BK; kk++) {
            float b4[4];
            *(float4*)b4 = *(const float4*)&Bs[kk][tx * 4];
            float a8[8];
#pragma unroll
            for (int r = 0; r < 8; r++) a8[r] = As[ty * 8 + r][kk];
#pragma unroll
            for (int r = 0; r < 8; r++)
#pragma unroll
                for (int c = 0; c < 4; c++)
                    acc[r][c] = fmaf(a8[r], b4[c], acc[r][c]);
        }
        __syncthreads();
    }

#pragma unroll
    for (int r = 0; r < 8; r++) {
        int m = bm + ty * 8 + r;
        if (m < M) {
            float v0 = acc[r][0] + bias[tx * 4 + 0];
            float v1 = acc[r][1] + bias[tx * 4 + 1];
            float v2 = acc[r][2] + bias[tx * 4 + 2];
            float v3 = acc[r][3] + bias[tx * 4 + 3];
            float* dst = &out[(size_t)m * H_DIM + tx * 4];
            dst[0] = v0; dst[1] = v1; dst[2] = v2; dst[3] = v3;
            // fp16 copy into jpack: node m, lane-group tx, bytes [8..16)
            uint2 p;
            *(__half2*)&p.x = __floats2half2_rn(v0, v1);
            *(__half2*)&p.y = __floats2half2_rn(v2, v3);
            *(uint2*)((char*)jpack + (size_t)m * 256 + tx * 16 + 8) = p;
        }
    }
}

// ---------------------------------------------------------------------------
// GEMM 2 (fused a1|a2, fp16 out): for q in [0,128):
//   weight element (out col q, k idx m) = att_w[(q&63)*144 + (q>>6)*64 + m]
//   q < 64 -> a1h[n][q],  q >= 64 -> a2 part of jpack[n]
// BM=128, BN=128, BK=16, K=64, 256 threads, 8x8 microtile.
// ---------------------------------------------------------------------------
struct alignas(16) H8 { __half2 h[4]; };

__global__ __launch_bounds__(256) void gemm_a12_kernel(
    const float* __restrict__ h,      // [M,64]
    const float* __restrict__ att_w,  // [64,144]
    __half* __restrict__ a1h,         // [M,64]
    __half* __restrict__ jpack,       // [M][256B]
    int M)
{
    __shared__ float As[BM][BK + 4];
    __shared__ float Bs[BK][128];

    const int tid = threadIdx.x;
    const int bm = blockIdx.x * BM;
    const int tx = tid & 15;
    const int ty = tid >> 4;

    float acc[8][8];
#pragma unroll
    for (int r = 0; r < 8; r++)
#pragma unroll
        for (int c = 0; c < 8; c++) acc[r][c] = 0.f;

    for (int k0 = 0; k0 < H_DIM; k0 += BK) {
#pragma unroll
        for (int it = 0; it < 2; it++) {
            int m = (tid >> 2) + it * 64;
            int kk = (tid & 3) * 4;
            float4 v = make_float4(0.f, 0.f, 0.f, 0.f);
            if (bm + m < M)
                v = *(const float4*)&h[(size_t)(bm + m) * H_DIM + k0 + kk];
            *(float4*)&As[m][kk] = v;
        }
        {
            int q = tid >> 1;
            int kk = (tid & 1) * 8;
            size_t base = (size_t)(q & 63) * ATT_LD + (q >> 6) * 64 + k0 + kk;
            float4 v0 = *(const float4*)&att_w[base];
            float4 v1 = *(const float4*)&att_w[base + 4];
            Bs[kk + 0][q] = v0.x; Bs[kk + 1][q] = v0.y;
            Bs[kk + 2][q] = v0.z; Bs[kk + 3][q] = v0.w;
            Bs[kk + 4][q] = v1.x; Bs[kk + 5][q] = v1.y;
            Bs[kk + 6][q] = v1.z; Bs[kk + 7][q] = v1.w;
        }
        __syncthreads();

#pragma unroll
        for (int kk = 0; kk < BK; kk++) {
            float b8[8];
            *(float4*)&b8[0] = *(const float4*)&Bs[kk][tx * 8];
            *(float4*)&b8[4] = *(const float4*)&Bs[kk][tx * 8 + 4];
            float a8[8];
#pragma unroll
            for (int r = 0; r < 8; r++) a8[r] = As[ty * 8 + r][kk];
#pragma unroll
            for (int r = 0; r < 8; r++)
#pragma unroll
                for (int c = 0; c < 8; c++)
                    acc[r][c] = fmaf(a8[r], b8[c], acc[r][c]);
        }
        __syncthreads();
    }

    const int q0 = tx * 8;
#pragma unroll
    for (int r = 0; r < 8; r++) {
        int m = bm + ty * 8 + r;
        if (m < M) {
            __half2 p0 = __floats2half2_rn(acc[r][0], acc[r][1]);
            __half2 p1 = __floats2half2_rn(acc[r][2], acc[r][3]);
            __half2 p2 = __floats2half2_rn(acc[r][4], acc[r][5]);
            __half2 p3 = __floats2half2_rn(acc[r][6], acc[r][7]);
            if (q0 < 64) {
                H8 v; v.h[0] = p0; v.h[1] = p1; v.h[2] = p2; v.h[3] = p3;
                *(H8*)(a1h + (size_t)m * H_DIM + q0) = v;
            } else {
                // a2 channels cb..cb+7 -> lane-groups g0,g0+1, bytes [0..8)
                int cb = q0 - 64;
                int g0 = cb >> 2;
                uint2 u0, u1;
                *(__half2*)&u0.x = p0; *(__half2*)&u0.y = p1;
                *(__half2*)&u1.x = p2; *(__half2*)&u1.y = p3;
                char* base = (char*)jpack + (size_t)m * 256;
                *(uint2*)(base + g0 * 16)        = u0;
                *(uint2*)(base + (g0 + 1) * 16)  = u1;
            }
        }
    }
}

// ---------------------------------------------------------------------------
// Edge phase v4: half-warp per edge, 4 channels per lane, 2x unroll.
//   s = leaky( a1[i] + a2[j] + W3 @ ea[e] + att_b )
//   out[i] += h[j] * s        (red.global.add.v4.f32)
// W3 rows for the lane's 4 channels live in 16 float4 registers.
// ea broadcast across the half-warp via shuffles.
// j-side gather is a single LDG.128 (packed a2|h fp16).
// Index dtype detected inline per warp via ballot.
// ---------------------------------------------------------------------------
__device__ __forceinline__ float4 h4_to_f4(uint2 v)
{
    float2 l = __half22float2(*(__half2*)&v.x);
    float2 h = __half22float2(*(__half2*)&v.y);
    return make_float4(l.x, l.y, h.x, h.y);
}

__device__ __forceinline__ float4 leaky4(float4 s)
{
    s.x = fmaxf(s.x, 0.f) + 0.2f * fminf(s.x, 0.f);
    s.y = fmaxf(s.y, 0.f) + 0.2f * fminf(s.y, 0.f);
    s.z = fmaxf(s.z, 0.f) + 0.2f * fminf(s.z, 0.f);
    s.w = fmaxf(s.w, 0.f) + 0.2f * fminf(s.w, 0.f);
    return s;
}

__device__ __forceinline__ void red_add_v4(float* p, float4 v)
{
    asm volatile("red.global.add.v4.f32 [%0], {%1, %2, %3, %4};"
                 :: "l"(p), "f"(v.x), "f"(v.y), "f"(v.z), "f"(v.w)
                 : "memory");
}

__global__ __launch_bounds__(256, 2) void edge_kernel_v4(
    const void* __restrict__ ei_raw,     // [2,E] int32 or int64
    const float* __restrict__ ea,        // [E,16] fp32
    const float* __restrict__ att_w,     // [64,144]
    const float* __restrict__ att_b,     // [64]
    const __half* __restrict__ a1h,      // [N,64]
    const __half* __restrict__ jpack,    // [N][256B]
    float* __restrict__ out,             // [N,64]
    int E, int N)
{
    const int tid   = threadIdx.x;
    const int lane  = tid & 31;
    const int glane = lane & 15;
    const int hw    = (blockIdx.x * (blockDim.x >> 5) + (tid >> 5)) * 2 + (lane >> 4);
    const int T     = gridDim.x * (blockDim.x >> 5) * 2;   // total half-warps
    const int k0    = 4 * glane;
    const int shfl_base = lane & 16;

    const long long* ei64 = (const long long*)ei_raw;
    const int*       ei32 = (const int*)ei_raw;

    // Inline dtype detect: int32 data seen as int64 has random high words.
    int is64;
    {
        long long v = ei64[lane];
        unsigned ok = __ballot_sync(0xffffffffu, v >= 0 && v < (long long)N);
        is64 = (ok == 0xffffffffu);
    }

    // W3 rows for this lane's 4 channels: w3r[c] = att_w[k0+0..3][128+c]
    float4 w3r[E_FEAT];
#pragma unroll
    for (int c = 0; c < E_FEAT; c++) {
        w3r[c].x = att_w[(size_t)(k0 + 0) * ATT_LD + 2 * H_DIM + c];
        w3r[c].y = att_w[(size_t)(k0 + 1) * ATT_LD + 2 * H_DIM + c];
        w3r[c].z = att_w[(size_t)(k0 + 2) * ATT_LD + 2 * H_DIM + c];
        w3r[c].w = att_w[(size_t)(k0 + 3) * ATT_LD + 2 * H_DIM + c];
    }
    const float4 bias4 = *(const float4*)&att_b[k0];

    const uint2* a1v = (const uint2*)a1h;    // [N][16] x 8B
    const uint4* jp  = (const uint4*)jpack;  // [N][16] x 16B

    for (int e1 = hw; e1 < E; e1 += 2 * T) {
        const int  e2  = e1 + T;
        const bool v2  = e2 < E;
        const int  e2c = v2 ? e2 : e1;

        int i1, j1, i2, j2;
        if (is64) {
            i1 = (int)ei64[e1];  j1 = (int)ei64[(size_t)E + e1];
            i2 = (int)ei64[e2c]; j2 = (int)ei64[(size_t)E + e2c];
        } else {
            i1 = ei32[e1];  j1 = ei32[(size_t)E + e1];
            i2 = ei32[e2c]; j2 = ei32[(size_t)E + e2c];
        }

        float eav1 = ea[(size_t)e1  * E_FEAT + glane];
        float eav2 = ea[(size_t)e2c * E_FEAT + glane];

        const uint2 A1a = a1v[(size_t)i1 * 16 + glane];
        const uint4 JPa = jp[(size_t)j1 * 16 + glane];
        const uint2 A1b = a1v[(size_t)i2 * 16 + glane];
        const uint4 JPb = jp[(size_t)j2 * 16 + glane];

        float4 f1 = h4_to_f4(A1a);
        float4 g1 = h4_to_f4(make_uint2(JPa.x, JPa.y));  // a2[j1]
        float4 f2 = h4_to_f4(A1b);
        float4 g2 = h4_to_f4(make_uint2(JPb.x, JPb.y));  // a2[j2]

        float4 s1 = make_float4(bias4.x + f1.x + g1.x, bias4.y + f1.y + g1.y,
                                bias4.z + f1.z + g1.z, bias4.w + f1.w + g1.w);
        float4 s2 = make_float4(bias4.x + f2.x + g2.x, bias4.y + f2.y + g2.y,
                                bias4.z + f2.z + g2.z, bias4.w + f2.w + g2.w);

#pragma unroll
        for (int c = 0; c < E_FEAT; c++) {
            float ec1 = __shfl_sync(0xffffffffu, eav1, shfl_base + c);
            float ec2 = __shfl_sync(0xffffffffu, eav2, shfl_base + c);
            s1.x = fmaf(w3r[c].x, ec1, s1.x);  s2.x = fmaf(w3r[c].x, ec2, s2.x);
            s1.y = fmaf(w3r[c].y, ec1, s1.y);  s2.y = fmaf(w3r[c].y, ec2, s2.y);
            s1.z = fmaf(w3r[c].z, ec1, s1.z);  s2.z = fmaf(w3r[c].z, ec2, s2.z);
            s1.w = fmaf(w3r[c].w, ec1, s1.w);  s2.w = fmaf(w3r[c].w, ec2, s2.w);
        }

        s1 = leaky4(s1);
        s2 = leaky4(s2);

        float4 HJ1 = h4_to_f4(make_uint2(JPa.z, JPa.w));  // h[j1]
        float4 m1 = make_float4(HJ1.x * s1.x, HJ1.y * s1.y,
                                HJ1.z * s1.z, HJ1.w * s1.w);
        red_add_v4(&out[(size_t)i1 * H_DIM + k0], m1);

        if (v2) {
            float4 HJ2 = h4_to_f4(make_uint2(JPb.z, JPb.w));  // h[j2]
            float4 m2 = make_float4(HJ2.x * s2.x, HJ2.y * s2.y,
                                    HJ2.z * s2.z, HJ2.w * s2.w);
            red_add_v4(&out[(size_t)i2 * H_DIM + k0], m2);
        }
    }
}

// ---------------------------------------------------------------------------
// Launch
// Inputs (metadata order): x, edge_index, edge_attr, fc_w, fc_b, att_w, att_b
// ---------------------------------------------------------------------------
extern "C" void kernel_launch(void* const* d_in, const int* in_sizes, int n_in,
                              void* d_out, int out_size)
{
    const float* x     = (const float*)d_in[0];
    const void*  ei    = d_in[1];
    const float* ea    = (const float*)d_in[2];
    const float* fc_w  = (const float*)d_in[3];
    const float* fc_b  = (const float*)d_in[4];
    const float* att_w = (const float*)d_in[5];
    const float* att_b = (const float*)d_in[6];
    float*       out   = (float*)d_out;

    const int N = in_sizes[0] / C_DIM;
    const int E = in_sizes[1] / 2;

    float*  hbuf  = nullptr;
    __half* a1buf = nullptr;
    __half* jpbuf = nullptr;
    cudaGetSymbolAddress((void**)&hbuf,  g_h);
    cudaGetSymbolAddress((void**)&a1buf, g_a1h);
    cudaGetSymbolAddress((void**)&jpbuf, g_jpack);

    const int gblocks = (N + BM - 1) / BM;

    // zero output (async memset — graph-capturable)
    cudaMemsetAsync(out, 0, (size_t)N * H_DIM * sizeof(float));

    // h = x @ fc_w^T + fc_b   (fp32 + fp16 into jpack)
    gemm_h_kernel<<<gblocks, 256>>>(x, fc_w, fc_b, hbuf, jpbuf, N);
    // a1 (fp16) | a2 (fp16 into jpack) = h @ [W1|W2]^T
    gemm_a12_kernel<<<gblocks, 256>>>(hbuf, att_w, a1buf, jpbuf, N);

    // fused edge scatter (W3·ea computed inline)
    edge_kernel_v4<<<592, 256>>>(ei, ea, att_w, att_b, a1buf, jpbuf, out, E, N);
}